// round 16
// baseline (speedup 1.0000x reference)
#include <cuda_runtime.h>
#include <cuda_fp16.h>
#include <cstdint>

#define Bb 4
#define Hh 16
#define Ll 8192
#define Dd 64
#define BH (Bb*Hh)
#define SCALE 0.10511205190671431f   // 8192^(-1/4)
#define NCHUNK 16
#define RPC (Ll/NCHUNK)              // 512 rows per chunk
#define NTILE (RPC/64)               // 8 tiles of 64 rows
#define PAD 72                       // f16 row stride (144B, conflict-free)
#define P2ROWS 256                   // rows per phase2 CTA
#define P2TILES (P2ROWS/64)          // 4

// __device__ scratch (allocation-free rule)
__device__ float g_scratch[(size_t)NCHUNK*BH*Dd*Dd];   // 16.7 MB fp32 partial KV
__device__ __half g_KVh[(size_t)BH*Dd*Dd];             // 0.5 MB fp16 KV

// ---------------- helpers ----------------
__device__ __forceinline__ uint32_t s2u(const void* p) {
    uint32_t a;
    asm("{ .reg .u64 t; cvta.to.shared.u64 t, %1; cvt.u32.u64 %0, t; }" : "=r"(a) : "l"(p));
    return a;
}
__device__ __forceinline__ void ldsm4t(uint32_t addr, uint32_t* r) {
    asm volatile("ldmatrix.sync.aligned.m8n8.x4.trans.shared.b16 {%0,%1,%2,%3}, [%4];"
                 : "=r"(r[0]), "=r"(r[1]), "=r"(r[2]), "=r"(r[3]) : "r"(addr));
}
__device__ __forceinline__ void ldsm4(uint32_t addr, uint32_t* r) {
    asm volatile("ldmatrix.sync.aligned.m8n8.x4.shared.b16 {%0,%1,%2,%3}, [%4];"
                 : "=r"(r[0]), "=r"(r[1]), "=r"(r[2]), "=r"(r[3]) : "r"(addr));
}
// fp16 MMA, fp32 accumulate
__device__ __forceinline__ void mma16816(float* c, const uint32_t* a, uint32_t b0, uint32_t b1) {
    asm volatile("mma.sync.aligned.m16n8k16.row.col.f32.f16.f16.f32 "
                 "{%0,%1,%2,%3},{%4,%5,%6,%7},{%8,%9},{%0,%1,%2,%3};"
                 : "+f"(c[0]), "+f"(c[1]), "+f"(c[2]), "+f"(c[3])
                 : "r"(a[0]), "r"(a[1]), "r"(a[2]), "r"(a[3]), "r"(b0), "r"(b1));
}
__device__ __forceinline__ float elu_p1(float x) { float e = __expf(x); return x > 0.0f ? x + 1.0f : e; }
// pack (a -> lo half, b -> hi half) as fp16x2
__device__ __forceinline__ uint32_t pkh(float a, float b) {
    uint32_t r;
    asm("cvt.rn.f16x2.f32 %0, %1, %2;" : "=r"(r) : "f"(b), "f"(a));
    return r;
}

// ============================================================
// Phase 1 (R14, 53.6us measured): partial KV = Kf^T @ Vm (fp16 single-pass)
// grid (NCHUNK, BH), 256 thr / 8 warps.
// Per tile: sync -> TRANSFORM(regs) -> LDG(t+1) -> sync -> MMA
// ============================================================
__global__ void __launch_bounds__(256)
phase1_kernel(const float* __restrict__ Kp, const float* __restrict__ Vp,
              const float* __restrict__ maskp, const float* __restrict__ pip,
              const float* __restrict__ mup) {
    __shared__ __half khs[64*PAD], vhs[64*PAD];
    __shared__ float mus[64];
    const int t = threadIdx.x, lane = t & 31, w = t >> 5;
    const int chunk = blockIdx.x, bhidx = blockIdx.y, b = bhidx / Hh, h = bhidx % Hh;

    const float p0 = fminf(fmaxf(pip[0], 0.f), 1.f);
    const float p1 = fminf(fmaxf(pip[1], 0.f), 1.f);
    const float ps = p0 + p1;
    if (t < 64) mus[t] = p0 * mup[h*64 + t] + p1 * mup[(Hh + h)*64 + t];

    const size_t base = ((size_t)bhidx*Ll + (size_t)chunk*RPC) * 64;
    const float* __restrict__ Kb = Kp + base;
    const float* __restrict__ Vb = Vp + base;
    const float* __restrict__ mb = maskp + (size_t)b*Ll + (size_t)chunk*RPC;

    const int md = (w & 3) * 16, ne = (w >> 2) * 32;
    const int gr = lane >> 3, r8 = lane & 7;
    const uint32_t aoff = ((uint32_t)((((gr & 2) ? 8 : 0) + r8) * PAD + md + ((gr & 1) ? 8 : 0))) * 2;
    const uint32_t boff = ((uint32_t)((((gr & 1) ? 8 : 0) + r8) * PAD + ne + ((gr & 2) ? 8 : 0))) * 2;
    const uint32_t skh = s2u(khs), svh = s2u(vhs);

    float acc[4][4];
#pragma unroll
    for (int i = 0; i < 4; i++)
#pragma unroll
        for (int j = 0; j < 4; j++) acc[i][j] = 0.f;

    float4 kreg[4], vreg[4];
    float  mreg[4];
    const int trow = t >> 4, tdq = (t & 15) * 4;

#define LOAD_TILE(tl) do { const int _l0 = (tl) * 64; \
    _Pragma("unroll") \
    for (int j = 0; j < 4; j++) { \
        const size_t off = (size_t)(_l0 + trow + 16*j)*64 + tdq; \
        kreg[j] = *(const float4*)(Kb + off); \
        vreg[j] = *(const float4*)(Vb + off); \
        mreg[j] = mb[_l0 + trow + 16*j]; \
    } } while (0)

#define TRANSFORM() do { \
    _Pragma("unroll") \
    for (int j = 0; j < 4; j++) { \
        const int row = trow + 16*j; \
        const float m = mreg[j], msc = m * SCALE; \
        float f0 = elu_p1(kreg[j].x*ps - mus[tdq+0]) * msc; \
        float f1 = elu_p1(kreg[j].y*ps - mus[tdq+1]) * msc; \
        float f2 = elu_p1(kreg[j].z*ps - mus[tdq+2]) * msc; \
        float f3 = elu_p1(kreg[j].w*ps - mus[tdq+3]) * msc; \
        uint2 kh = { pkh(f0, f1), pkh(f2, f3) }; \
        *(uint2*)&khs[row*PAD + tdq] = kh; \
        uint2 vh = { pkh(vreg[j].x * m, vreg[j].y * m), pkh(vreg[j].z * m, vreg[j].w * m) }; \
        *(uint2*)&vhs[row*PAD + tdq] = vh; \
    } } while (0)

    LOAD_TILE(0);

    for (int tile = 0; tile < NTILE; tile++) {
        __syncthreads();                  // prev MMA done; mus visible on tile 0
        TRANSFORM();
        if (tile + 1 < NTILE) LOAD_TILE(tile + 1);
        __syncthreads();

#pragma unroll
        for (int kl = 0; kl < 64; kl += 16) {
            const uint32_t kadd = (uint32_t)(kl * PAD * 2);
            uint32_t ah[4];
            ldsm4t(skh + kadd + aoff, ah);
            uint32_t bh0[4], bh1[4];
            ldsm4t(svh + kadd + boff,      bh0);
            ldsm4t(svh + kadd + boff + 32, bh1);
            mma16816(acc[0], ah, bh0[0], bh0[1]);
            mma16816(acc[1], ah, bh0[2], bh0[3]);
            mma16816(acc[2], ah, bh1[0], bh1[1]);
            mma16816(acc[3], ah, bh1[2], bh1[3]);
        }
    }
#undef LOAD_TILE
#undef TRANSFORM

    float* outp = g_scratch + ((size_t)chunk*BH + bhidx) * 4096;
    const int rw = lane >> 2, cq = (lane & 3) * 2;
#pragma unroll
    for (int j = 0; j < 4; j++) {
        float2 lo = { acc[j][0], acc[j][1] };
        float2 hi = { acc[j][2], acc[j][3] };
        *(float2*)&outp[(md + rw) * 64 + ne + 8*j + cq]     = lo;
        *(float2*)&outp[(md + 8 + rw) * 64 + ne + 8*j + cq] = hi;
    }
}

// ============================================================
// Reduce: KV = sum over 16 chunks; emit fp16. grid (BH, 4), 256 thr.
// ============================================================
__global__ void __launch_bounds__(256)
reduce_kernel() {
    const int bhidx = blockIdx.x, part = blockIdx.y, t = threadIdx.x;
    const int pos = part*1024 + t*4;
    float4 s = make_float4(0.f, 0.f, 0.f, 0.f);
#pragma unroll
    for (int c = 0; c < NCHUNK; c++) {
        const float4 v = *(const float4*)(g_scratch + ((size_t)c*BH + bhidx)*4096 + pos);
        s.x += v.x; s.y += v.y; s.z += v.z; s.w += v.w;
    }
    uint2 hv = { pkh(s.x, s.y), pkh(s.z, s.w) };
    *(uint2*)(g_KVh + (size_t)bhidx*4096 + pos) = hv;
}

// ============================================================
// Phase 2: out[l][e] = sum_d Qf[l][d]*KV[d][e]  (fp16, register-resident KV)
// grid (Ll/P2ROWS, BH) = (32, 64), 256 thr / 8 warps.
// KV b-frags loaded ONCE into 32 regs; double-buffered Q tiles, 1 sync/tile:
//   per tile: LOADQ(t+1) -> MMA(t, KV-in-regs) -> TRANSQ(t+1) -> STG -> sync
// ============================================================
__global__ void __launch_bounds__(256)
phase2_kernel(const float* __restrict__ Qp, float* __restrict__ outp) {
    __shared__ __half kvs[64*PAD];
    __shared__ __half qhs[2][64*PAD];
    const int t = threadIdx.x, lane = t & 31, w = t >> 5;
    const int rb = blockIdx.x, bhidx = blockIdx.y;

    // KV tile into smem (L2-resident source)
    {
        const int row = t >> 2, cg = (t & 3) * 16;
        *(uint4*)&kvs[row*PAD + cg]     = *(const uint4*)(g_KVh + (size_t)bhidx*4096 + row*64 + cg);
        *(uint4*)&kvs[row*PAD + cg + 8] = *(const uint4*)(g_KVh + (size_t)bhidx*4096 + row*64 + cg + 8);
    }

    const float* __restrict__ Qb = Qp + ((size_t)bhidx*Ll + (size_t)rb*P2ROWS) * 64;
    float* __restrict__ Ob = outp + ((size_t)bhidx*Ll + (size_t)rb*P2ROWS) * 64;

    const int md = (w & 3) * 16, ne = (w >> 2) * 32;
    const int gr = lane >> 3, r8 = lane & 7;
    const uint32_t aoff = ((uint32_t)((md + ((gr & 1) ? 8 : 0) + r8) * PAD + ((gr & 2) ? 8 : 0))) * 2;
    const uint32_t boff = ((uint32_t)((((gr & 1) ? 8 : 0) + r8) * PAD + ne + ((gr & 2) ? 8 : 0))) * 2;
    const uint32_t svh = s2u(kvs);
    const uint32_t sq0 = s2u(qhs[0]), sq1 = s2u(qhs[1]);
    const int rw = lane >> 2, cq = (lane & 3) * 2;

    float4 qreg[4];
    const int trow = t >> 4, tdq = (t & 15) * 4;

#define LOADQ(tl) do { const int _l0 = (tl) * 64; \
    _Pragma("unroll") \
    for (int j = 0; j < 4; j++) { \
        qreg[j] = *(const float4*)(Qb + (size_t)(_l0 + trow + 16*j)*64 + tdq); \
    } } while (0)

#define TRANSQ(bf) do { \
    _Pragma("unroll") \
    for (int j = 0; j < 4; j++) { \
        const int row = trow + 16*j; \
        float f0 = elu_p1(qreg[j].x) * SCALE, f1 = elu_p1(qreg[j].y) * SCALE; \
        float f2 = elu_p1(qreg[j].z) * SCALE, f3 = elu_p1(qreg[j].w) * SCALE; \
        uint2 qh = { pkh(f0, f1), pkh(f2, f3) }; \
        *(uint2*)&qhs[bf][row*PAD + tdq] = qh; \
    } } while (0)

    LOADQ(0);
    TRANSQ(0);
    __syncthreads();   // kvs + qhs[0] visible

    // hoist KV b-frags: invariant across all tiles (32 regs)
    uint32_t bfrag[8][4];
#pragma unroll
    for (int kd4 = 0; kd4 < 4; kd4++)
#pragma unroll
        for (int p = 0; p < 2; p++)
            ldsm4t(svh + (uint32_t)(kd4 * 16 * PAD * 2 + p * 32) + boff, bfrag[kd4*2 + p]);

    for (int tile = 0; tile < P2TILES; tile++) {
        const int buf = tile & 1;
        if (tile + 1 < P2TILES) LOADQ(tile + 1);
        const uint32_t sq = buf ? sq1 : sq0;

        float acc[4][4];
#pragma unroll
        for (int i = 0; i < 4; i++)
#pragma unroll
            for (int j = 0; j < 4; j++) acc[i][j] = 0.f;

#pragma unroll
        for (int kd4 = 0; kd4 < 4; kd4++) {
            uint32_t ah[4];
            ldsm4(sq + aoff + (uint32_t)(kd4 * 32), ah);
#pragma unroll
            for (int p = 0; p < 2; p++) {
                mma16816(acc[2*p],   ah, bfrag[kd4*2+p][0], bfrag[kd4*2+p][1]);
                mma16816(acc[2*p+1], ah, bfrag[kd4*2+p][2], bfrag[kd4*2+p][3]);
            }
        }

        if (tile + 1 < P2TILES) TRANSQ(buf ^ 1);   // fills other buffer under MMA drain

        float* __restrict__ ob = Ob + (size_t)tile*64*64;
#pragma unroll
        for (int j = 0; j < 4; j++) {
            float2 lo = { acc[j][0], acc[j][1] };
            float2 hi = { acc[j][2], acc[j][3] };
            *(float2*)&ob[(md + rw) * 64 + ne + 8*j + cq]     = lo;
            *(float2*)&ob[(md + 8 + rw) * 64 + ne + 8*j + cq] = hi;
        }
        __syncthreads();   // qhs[buf^1] complete before next tile's MMA
    }
#undef LOADQ
#undef TRANSQ
}

// ============================================================
// Launch
// ============================================================
extern "C" void kernel_launch(void* const* d_in, const int* in_sizes, int n_in,
                              void* d_out, int out_size) {
    const float* Q    = (const float*)d_in[0];
    const float* K    = (const float*)d_in[1];
    const float* V    = (const float*)d_in[2];
    const float* mask = (const float*)d_in[3];
    const float* pi   = (const float*)d_in[4];
    const float* mu   = (const float*)d_in[5];
    float* out = (float*)d_out;

    dim3 g1(NCHUNK, BH);
    phase1_kernel<<<g1, 256>>>(K, V, mask, pi, mu);
    dim3 g2(BH, 4);
    reduce_kernel<<<g2, 256>>>();
    dim3 g3(Ll / P2ROWS, BH);
    phase2_kernel<<<g3, 256>>>(Q, out);
}

// round 17
// speedup vs baseline: 1.0153x; 1.0153x over previous
#include <cuda_runtime.h>
#include <cuda_fp16.h>
#include <cstdint>

#define Bb 4
#define Hh 16
#define Ll 8192
#define Dd 64
#define BH (Bb*Hh)
#define SCALE 0.10511205190671431f   // 8192^(-1/4)
#define NCHUNK 16
#define RPC (Ll/NCHUNK)              // 512 rows per chunk
#define NTILE (RPC/64)               // 8 tiles of 64 rows
#define PAD 72                       // f16 row stride (144B, conflict-free)
#define P2ROWS 256                   // rows per phase2 CTA
#define P2TILE 128                   // rows per phase2 tile
#define P2TILES (P2ROWS/P2TILE)      // 2

// __device__ scratch (allocation-free rule)
__device__ float g_scratch[(size_t)NCHUNK*BH*Dd*Dd];   // 16.7 MB fp32 partial KV
__device__ __half g_KVh[(size_t)BH*Dd*Dd];             // 0.5 MB fp16 KV

// ---------------- helpers ----------------
__device__ __forceinline__ uint32_t s2u(const void* p) {
    uint32_t a;
    asm("{ .reg .u64 t; cvta.to.shared.u64 t, %1; cvt.u32.u64 %0, t; }" : "=r"(a) : "l"(p));
    return a;
}
__device__ __forceinline__ void ldsm4t(uint32_t addr, uint32_t* r) {
    asm volatile("ldmatrix.sync.aligned.m8n8.x4.trans.shared.b16 {%0,%1,%2,%3}, [%4];"
                 : "=r"(r[0]), "=r"(r[1]), "=r"(r[2]), "=r"(r[3]) : "r"(addr));
}
__device__ __forceinline__ void ldsm4(uint32_t addr, uint32_t* r) {
    asm volatile("ldmatrix.sync.aligned.m8n8.x4.shared.b16 {%0,%1,%2,%3}, [%4];"
                 : "=r"(r[0]), "=r"(r[1]), "=r"(r[2]), "=r"(r[3]) : "r"(addr));
}
// fp16 MMA, fp32 accumulate
__device__ __forceinline__ void mma16816(float* c, const uint32_t* a, uint32_t b0, uint32_t b1) {
    asm volatile("mma.sync.aligned.m16n8k16.row.col.f32.f16.f16.f32 "
                 "{%0,%1,%2,%3},{%4,%5,%6,%7},{%8,%9},{%0,%1,%2,%3};"
                 : "+f"(c[0]), "+f"(c[1]), "+f"(c[2]), "+f"(c[3])
                 : "r"(a[0]), "r"(a[1]), "r"(a[2]), "r"(a[3]), "r"(b0), "r"(b1));
}
__device__ __forceinline__ float elu_p1(float x) { float e = __expf(x); return x > 0.0f ? x + 1.0f : e; }
// pack (a -> lo half, b -> hi half) as fp16x2
__device__ __forceinline__ uint32_t pkh(float a, float b) {
    uint32_t r;
    asm("cvt.rn.f16x2.f32 %0, %1, %2;" : "=r"(r) : "f"(b), "f"(a));
    return r;
}

// ============================================================
// Phase 1 (R14, 53.6us measured): partial KV = Kf^T @ Vm (fp16 single-pass)
// grid (NCHUNK, BH), 256 thr / 8 warps.
// Per tile: sync -> TRANSFORM(regs) -> LDG(t+1) -> sync -> MMA
// ============================================================
__global__ void __launch_bounds__(256)
phase1_kernel(const float* __restrict__ Kp, const float* __restrict__ Vp,
              const float* __restrict__ maskp, const float* __restrict__ pip,
              const float* __restrict__ mup) {
    __shared__ __half khs[64*PAD], vhs[64*PAD];
    __shared__ float mus[64];
    const int t = threadIdx.x, lane = t & 31, w = t >> 5;
    const int chunk = blockIdx.x, bhidx = blockIdx.y, b = bhidx / Hh, h = bhidx % Hh;

    const float p0 = fminf(fmaxf(pip[0], 0.f), 1.f);
    const float p1 = fminf(fmaxf(pip[1], 0.f), 1.f);
    const float ps = p0 + p1;
    if (t < 64) mus[t] = p0 * mup[h*64 + t] + p1 * mup[(Hh + h)*64 + t];

    const size_t base = ((size_t)bhidx*Ll + (size_t)chunk*RPC) * 64;
    const float* __restrict__ Kb = Kp + base;
    const float* __restrict__ Vb = Vp + base;
    const float* __restrict__ mb = maskp + (size_t)b*Ll + (size_t)chunk*RPC;

    const int md = (w & 3) * 16, ne = (w >> 2) * 32;
    const int gr = lane >> 3, r8 = lane & 7;
    const uint32_t aoff = ((uint32_t)((((gr & 2) ? 8 : 0) + r8) * PAD + md + ((gr & 1) ? 8 : 0))) * 2;
    const uint32_t boff = ((uint32_t)((((gr & 1) ? 8 : 0) + r8) * PAD + ne + ((gr & 2) ? 8 : 0))) * 2;
    const uint32_t skh = s2u(khs), svh = s2u(vhs);

    float acc[4][4];
#pragma unroll
    for (int i = 0; i < 4; i++)
#pragma unroll
        for (int j = 0; j < 4; j++) acc[i][j] = 0.f;

    float4 kreg[4], vreg[4];
    float  mreg[4];
    const int trow = t >> 4, tdq = (t & 15) * 4;

#define LOAD_TILE(tl) do { const int _l0 = (tl) * 64; \
    _Pragma("unroll") \
    for (int j = 0; j < 4; j++) { \
        const size_t off = (size_t)(_l0 + trow + 16*j)*64 + tdq; \
        kreg[j] = *(const float4*)(Kb + off); \
        vreg[j] = *(const float4*)(Vb + off); \
        mreg[j] = mb[_l0 + trow + 16*j]; \
    } } while (0)

#define TRANSFORM() do { \
    _Pragma("unroll") \
    for (int j = 0; j < 4; j++) { \
        const int row = trow + 16*j; \
        const float m = mreg[j], msc = m * SCALE; \
        float f0 = elu_p1(kreg[j].x*ps - mus[tdq+0]) * msc; \
        float f1 = elu_p1(kreg[j].y*ps - mus[tdq+1]) * msc; \
        float f2 = elu_p1(kreg[j].z*ps - mus[tdq+2]) * msc; \
        float f3 = elu_p1(kreg[j].w*ps - mus[tdq+3]) * msc; \
        uint2 kh = { pkh(f0, f1), pkh(f2, f3) }; \
        *(uint2*)&khs[row*PAD + tdq] = kh; \
        uint2 vh = { pkh(vreg[j].x * m, vreg[j].y * m), pkh(vreg[j].z * m, vreg[j].w * m) }; \
        *(uint2*)&vhs[row*PAD + tdq] = vh; \
    } } while (0)

    LOAD_TILE(0);

    for (int tile = 0; tile < NTILE; tile++) {
        __syncthreads();                  // prev MMA done; mus visible on tile 0
        TRANSFORM();
        if (tile + 1 < NTILE) LOAD_TILE(tile + 1);
        __syncthreads();

#pragma unroll
        for (int kl = 0; kl < 64; kl += 16) {
            const uint32_t kadd = (uint32_t)(kl * PAD * 2);
            uint32_t ah[4];
            ldsm4t(skh + kadd + aoff, ah);
            uint32_t bh0[4], bh1[4];
            ldsm4t(svh + kadd + boff,      bh0);
            ldsm4t(svh + kadd + boff + 32, bh1);
            mma16816(acc[0], ah, bh0[0], bh0[1]);
            mma16816(acc[1], ah, bh0[2], bh0[3]);
            mma16816(acc[2], ah, bh1[0], bh1[1]);
            mma16816(acc[3], ah, bh1[2], bh1[3]);
        }
    }
#undef LOAD_TILE
#undef TRANSFORM

    float* outp = g_scratch + ((size_t)chunk*BH + bhidx) * 4096;
    const int rw = lane >> 2, cq = (lane & 3) * 2;
#pragma unroll
    for (int j = 0; j < 4; j++) {
        float2 lo = { acc[j][0], acc[j][1] };
        float2 hi = { acc[j][2], acc[j][3] };
        *(float2*)&outp[(md + rw) * 64 + ne + 8*j + cq]     = lo;
        *(float2*)&outp[(md + 8 + rw) * 64 + ne + 8*j + cq] = hi;
    }
}

// ============================================================
// Reduce: KV = sum over 16 chunks; emit fp16. grid (BH, 4), 256 thr.
// ============================================================
__global__ void __launch_bounds__(256)
reduce_kernel() {
    const int bhidx = blockIdx.x, part = blockIdx.y, t = threadIdx.x;
    const int pos = part*1024 + t*4;
    float4 s = make_float4(0.f, 0.f, 0.f, 0.f);
#pragma unroll
    for (int c = 0; c < NCHUNK; c++) {
        const float4 v = *(const float4*)(g_scratch + ((size_t)c*BH + bhidx)*4096 + pos);
        s.x += v.x; s.y += v.y; s.z += v.z; s.w += v.w;
    }
    uint2 hv = { pkh(s.x, s.y), pkh(s.z, s.w) };
    *(uint2*)(g_KVh + (size_t)bhidx*4096 + pos) = hv;
}

// ============================================================
// Phase 2: out[l][e] = sum_d Qf[l][d]*KV[d][e]  (fp16, 32x32 warp tiles)
// grid (Ll/P2ROWS, BH) = (32, 64), 256 thr / 8 warps.
// CTA: KV once, then 2 tiles of 128 Q rows; warp (w&3): 32-row group,
// (w>>2): 32-col half. Per kd: 2 a-ldsm + 2 b-ldsm + 8 MMAs (33% less ldsm).
// Per tile: sync -> TRANSQ(regs) -> LOADQ(t+1) -> sync -> MMA+STG
// ============================================================
__global__ void __launch_bounds__(256)
phase2_kernel(const float* __restrict__ Qp, float* __restrict__ outp) {
    __shared__ __half qhs[P2TILE*PAD];   // 128 rows
    __shared__ __half kvs[64*PAD];
    const int t = threadIdx.x, lane = t & 31, w = t >> 5;
    const int rb = blockIdx.x, bhidx = blockIdx.y;

    // KV tile once per CTA (L2-resident source)
    {
        const int row = t >> 2, cg = (t & 3) * 16;
        *(uint4*)&kvs[row*PAD + cg]     = *(const uint4*)(g_KVh + (size_t)bhidx*4096 + row*64 + cg);
        *(uint4*)&kvs[row*PAD + cg + 8] = *(const uint4*)(g_KVh + (size_t)bhidx*4096 + row*64 + cg + 8);
    }

    const float* __restrict__ Qb = Qp + ((size_t)bhidx*Ll + (size_t)rb*P2ROWS) * 64;
    float* __restrict__ Ob = outp + ((size_t)bhidx*Ll + (size_t)rb*P2ROWS) * 64;

    const int mr = (w & 3) * 32;         // 32-row group
    const int ne = (w >> 2) * 32;        // 32-col half
    const int gr = lane >> 3, r8 = lane & 7;
    // a-frags (normal ldsm of Q [l][d]); second a-tile at +16 rows (= +32*PAD bytes)
    const uint32_t aoff = ((uint32_t)((mr + ((gr & 1) ? 8 : 0) + r8) * PAD + ((gr & 2) ? 8 : 0))) * 2;
    // b-frag (trans ldsm of KV [d][e])
    const uint32_t boff = ((uint32_t)((((gr & 1) ? 8 : 0) + r8) * PAD + ne + ((gr & 2) ? 8 : 0))) * 2;
    const uint32_t sqh = s2u(qhs), svh = s2u(kvs);
    const int rw = lane >> 2, cq = (lane & 3) * 2;

    float4 qreg[8];
    const int trow = t >> 4, tdq = (t & 15) * 4;   // rows trow + 16*j, j=0..7

#define LOADQ(tl) do { const int _l0 = (tl) * P2TILE; \
    _Pragma("unroll") \
    for (int j = 0; j < 8; j++) { \
        qreg[j] = *(const float4*)(Qb + (size_t)(_l0 + trow + 16*j)*64 + tdq); \
    } } while (0)

#define TRANSQ() do { \
    _Pragma("unroll") \
    for (int j = 0; j < 8; j++) { \
        const int row = trow + 16*j; \
        float f0 = elu_p1(qreg[j].x) * SCALE, f1 = elu_p1(qreg[j].y) * SCALE; \
        float f2 = elu_p1(qreg[j].z) * SCALE, f3 = elu_p1(qreg[j].w) * SCALE; \
        uint2 qh = { pkh(f0, f1), pkh(f2, f3) }; \
        *(uint2*)&qhs[row*PAD + tdq] = qh; \
    } } while (0)

    LOADQ(0);

    for (int tile = 0; tile < P2TILES; tile++) {
        __syncthreads();                  // prev MMA done; KV visible on tile 0
        TRANSQ();
        if (tile + 1 < P2TILES) LOADQ(tile + 1);
        __syncthreads();

        float acc[8][4];                  // [mi*4 + ni]: mi row-tile, ni n8-tile
#pragma unroll
        for (int i = 0; i < 8; i++)
#pragma unroll
            for (int j = 0; j < 4; j++) acc[i][j] = 0.f;

#pragma unroll
        for (int kd4 = 0; kd4 < 4; kd4++) {
            uint32_t a0[4], a1[4];
            ldsm4(sqh + aoff + (uint32_t)(kd4 * 32), a0);
            ldsm4(sqh + aoff + (uint32_t)(32 * PAD) + (uint32_t)(kd4 * 32), a1);
#pragma unroll
            for (int p = 0; p < 2; p++) {
                uint32_t bb[4];
                ldsm4t(svh + (uint32_t)(kd4 * 16 * PAD * 2 + p * 32) + boff, bb);
                mma16816(acc[0 + 2*p],     a0, bb[0], bb[1]);
                mma16816(acc[0 + 2*p + 1], a0, bb[2], bb[3]);
                mma16816(acc[4 + 2*p],     a1, bb[0], bb[1]);
                mma16816(acc[4 + 2*p + 1], a1, bb[2], bb[3]);
            }
        }

        float* __restrict__ ob = Ob + (size_t)tile*P2TILE*64;
#pragma unroll
        for (int mi = 0; mi < 2; mi++)
#pragma unroll
            for (int ni = 0; ni < 4; ni++) {
                const float* a = acc[mi*4 + ni];
                float2 lo = { a[0], a[1] };
                float2 hi = { a[2], a[3] };
                const int rbase = mr + 16*mi;
                *(float2*)&ob[(rbase + rw) * 64 + ne + 8*ni + cq]     = lo;
                *(float2*)&ob[(rbase + 8 + rw) * 64 + ne + 8*ni + cq] = hi;
            }
    }
#undef LOADQ
#undef TRANSQ
}

// ============================================================
// Launch
// ============================================================
extern "C" void kernel_launch(void* const* d_in, const int* in_sizes, int n_in,
                              void* d_out, int out_size) {
    const float* Q    = (const float*)d_in[0];
    const float* K    = (const float*)d_in[1];
    const float* V    = (const float*)d_in[2];
    const float* mask = (const float*)d_in[3];
    const float* pi   = (const float*)d_in[4];
    const float* mu   = (const float*)d_in[5];
    float* out = (float*)d_out;

    dim3 g1(NCHUNK, BH);
    phase1_kernel<<<g1, 256>>>(K, V, mask, pi, mu);
    dim3 g2(BH, 4);
    reduce_kernel<<<g2, 256>>>();
    dim3 g3(Ll / P2ROWS, BH);
    phase2_kernel<<<g3, 256>>>(Q, out);
}